// round 2
// baseline (speedup 1.0000x reference)
#include <cuda_runtime.h>
#include <math.h>

#define N_TOK   4096
#define D_MODEL 1024
#define D_FF    2048
#define N_EXP   8
#define ROWS    9216   /* 2*N_TOK (=8192) + worst-case per-expert padding (8*127 -> 9208) */
#define TILE    128

#define BM 128
#define BN 64
#define BK 16

// ---------------- scratch (static __device__ globals: allocation-free) ------
__device__ int   d_tok_exp[N_TOK * 2];
__device__ float d_tok_w[N_TOK * 2];
__device__ int   d_count[N_EXP];
__device__ int   d_off[N_EXP + 1];
__device__ int   d_cursor[N_EXP];
__device__ int   d_row_token[ROWS];
__device__ float d_row_weight[ROWS];
__device__ float d_H[(size_t)ROWS * D_FF];   // SwiGLU hidden, ~75.5 MB

// ---------------- kernel 0: zero output + row table + counters --------------
__global__ void init_kernel(float* __restrict__ out) {
    int i = blockIdx.x * blockDim.x + threadIdx.x;
    int stride = gridDim.x * blockDim.x;
    for (int j = i; j < N_TOK * D_MODEL; j += stride) out[j] = 0.f;
    if (i < ROWS) { d_row_token[i] = -1; d_row_weight[i] = 0.f; }
    if (i < N_EXP) d_count[i] = 0;
}

// ---------------- kernel 1: router (logits, softmax, top-2, counts) ---------
__global__ void router_kernel(const float* __restrict__ x,
                              const float* __restrict__ wr) {
    int warp = (blockIdx.x * blockDim.x + threadIdx.x) >> 5;
    int lane = threadIdx.x & 31;
    if (warp >= N_TOK) return;
    const float* xr = x + (size_t)warp * D_MODEL;

    float logits[N_EXP];
#pragma unroll
    for (int e = 0; e < N_EXP; e++) {
        const float* w = wr + e * D_MODEL;
        float p = 0.f;
        for (int d = lane; d < D_MODEL; d += 32) p = fmaf(xr[d], w[d], p);
#pragma unroll
        for (int s = 16; s > 0; s >>= 1) p += __shfl_xor_sync(0xffffffffu, p, s);
        logits[e] = p;
    }

    if (lane == 0) {
        float mx = -3.4e38f;
#pragma unroll
        for (int e = 0; e < N_EXP; e++) {
            float v = fminf(fmaxf(logits[e], -1e4f), 1e4f);
            logits[e] = v;
            mx = fmaxf(mx, v);
        }
        float ex[N_EXP], s = 0.f;
#pragma unroll
        for (int e = 0; e < N_EXP; e++) { ex[e] = expf(logits[e] - mx); s += ex[e]; }
        float denom = s + 1e-8f;
        float probs[N_EXP];
#pragma unroll
        for (int e = 0; e < N_EXP; e++)
            probs[e] = fminf(fmaxf(ex[e] / denom, 1e-8f), 1.0f);

        // top-2, strict > keeps lowest index on tie (matches lax.top_k)
        int i0 = 0;
#pragma unroll
        for (int e = 1; e < N_EXP; e++) if (probs[e] > probs[i0]) i0 = e;
        int i1 = (i0 == 0) ? 1 : 0;
#pragma unroll
        for (int e = 0; e < N_EXP; e++)
            if (e != i0 && probs[e] > probs[i1]) i1 = e;

        float p0 = probs[i0], p1 = probs[i1];
        float rs = 1.f / (p0 + p1 + 1e-8f);
        d_tok_exp[2 * warp]     = i0;
        d_tok_exp[2 * warp + 1] = i1;
        d_tok_w[2 * warp]       = p0 * rs;
        d_tok_w[2 * warp + 1]   = p1 * rs;
        atomicAdd(&d_count[i0], 1);
        atomicAdd(&d_count[i1], 1);
    }
}

// ---------------- kernel 2: padded segment offsets ---------------------------
__global__ void offsets_kernel() {
    if (threadIdx.x == 0) {
        int o = 0;
        for (int e = 0; e < N_EXP; e++) {
            d_off[e] = o;
            o += ((d_count[e] + TILE - 1) / TILE) * TILE;
            d_cursor[e] = 0;
        }
        d_off[N_EXP] = o;
    }
}

// ---------------- kernel 3: scatter (token,k) -> expert-sorted row -----------
__global__ void scatter_kernel() {
    int t = blockIdx.x * blockDim.x + threadIdx.x;
    if (t >= N_TOK) return;
#pragma unroll
    for (int k = 0; k < 2; k++) {
        int e = d_tok_exp[2 * t + k];
        int pos = d_off[e] + atomicAdd(&d_cursor[e], 1);
        d_row_token[pos]  = t;
        d_row_weight[pos] = d_tok_w[2 * t + k];
    }
}

// ---------------- kernel 4: GEMM1 (gate & up) + fused SwiGLU -> d_H ----------
// Per block: 128 rows x 64 f-cols, computing BOTH gate[128x64] and up[128x64]
// from shared A (gathered x rows). K = D_MODEL = 1024.
__global__ __launch_bounds__(256, 2)
void gemm1_kernel(const float* __restrict__ x, const float* __restrict__ wgu) {
    __shared__ float As[BK][BM];
    __shared__ float Bgs[BK][BN];
    __shared__ float Bus[BK][BN];
    __shared__ int   stok[BM];
    __shared__ int   sE;

    const int tid = threadIdx.x;
    const int rowStart = blockIdx.y * BM;
    const int colStart = blockIdx.x * BN;   // f in [0, D_FF)

    if (tid == 0) {
        int e = 0;
        for (int i = N_EXP - 1; i >= 0; i--)
            if (rowStart >= d_off[i]) { e = i; break; }
        sE = e;
    }
    if (tid < BM) stok[tid] = d_row_token[rowStart + tid];
    __syncthreads();

    const int e = sE;
    const float* Wg = wgu + (size_t)e * (2 * D_FF) * D_MODEL + (size_t)colStart * D_MODEL;
    const float* Wu = Wg + (size_t)D_FF * D_MODEL;

    float accG[8][4], accU[8][4];
#pragma unroll
    for (int i = 0; i < 8; i++)
#pragma unroll
        for (int j = 0; j < 4; j++) { accG[i][j] = 0.f; accU[i][j] = 0.f; }

    const int m0 = (tid >> 4) * 8;     // 16 groups of 8 rows
    const int n0 = (tid & 15) * 4;     // 16 groups of 4 cols
    const int lr = tid >> 2;           // 0..63
    const int lk = (tid & 3) * 4;      // 0,4,8,12

    for (int k0 = 0; k0 < D_MODEL; k0 += BK) {
        // A: 128x16 gather-load (pad rows -> 0)
#pragma unroll
        for (int it = 0; it < 2; it++) {
            int m = lr + it * 64;
            int t = stok[m];
            float4 v = make_float4(0.f, 0.f, 0.f, 0.f);
            if (t >= 0)
                v = *reinterpret_cast<const float4*>(x + (size_t)t * D_MODEL + k0 + lk);
            As[lk + 0][m] = v.x; As[lk + 1][m] = v.y;
            As[lk + 2][m] = v.z; As[lk + 3][m] = v.w;
        }
        // B: gate and up tiles, 64x16 each
        {
            float4 vg = *reinterpret_cast<const float4*>(Wg + (size_t)lr * D_MODEL + k0 + lk);
            Bgs[lk + 0][lr] = vg.x; Bgs[lk + 1][lr] = vg.y;
            Bgs[lk + 2][lr] = vg.z; Bgs[lk + 3][lr] = vg.w;
            float4 vu = *reinterpret_cast<const float4*>(Wu + (size_t)lr * D_MODEL + k0 + lk);
            Bus[lk + 0][lr] = vu.x; Bus[lk + 1][lr] = vu.y;
            Bus[lk + 2][lr] = vu.z; Bus[lk + 3][lr] = vu.w;
        }
        __syncthreads();

#pragma unroll
        for (int k = 0; k < BK; k++) {
            float a[8], bg[4], bu[4];
#pragma unroll
            for (int i = 0; i < 8; i++) a[i] = As[k][m0 + i];
#pragma unroll
            for (int j = 0; j < 4; j++) { bg[j] = Bgs[k][n0 + j]; bu[j] = Bus[k][n0 + j]; }
#pragma unroll
            for (int i = 0; i < 8; i++)
#pragma unroll
                for (int j = 0; j < 4; j++) {
                    accG[i][j] = fmaf(a[i], bg[j], accG[i][j]);
                    accU[i][j] = fmaf(a[i], bu[j], accU[i][j]);
                }
        }
        __syncthreads();
    }

    // epilogue: hidden = silu(up) * gate
#pragma unroll
    for (int i = 0; i < 8; i++) {
        float* hrow = d_H + (size_t)(rowStart + m0 + i) * D_FF + colStart + n0;
#pragma unroll
        for (int j = 0; j < 4; j++) {
            float u = accU[i][j], g = accG[i][j];
            float sg = 1.f / (1.f + expf(-u));
            hrow[j] = g * u * sg;
        }
    }
}

// ---------------- kernel 5: GEMM2 (down) + weighted scatter-add --------------
// Per block: 128 rows x 64 d-cols. K = D_FF = 2048.
__global__ __launch_bounds__(256, 2)
void gemm2_kernel(const float* __restrict__ wd, float* __restrict__ out) {
    __shared__ float As[BK][BM];
    __shared__ float Bs[BK][BN];
    __shared__ int   stok[BM];
    __shared__ float swt[BM];
    __shared__ int   sE;

    const int tid = threadIdx.x;
    const int rowStart = blockIdx.y * BM;
    const int colStart = blockIdx.x * BN;   // d in [0, D_MODEL)

    if (tid == 0) {
        int e = 0;
        for (int i = N_EXP - 1; i >= 0; i--)
            if (rowStart >= d_off[i]) { e = i; break; }
        sE = e;
    }
    if (tid < BM) {
        stok[tid] = d_row_token[rowStart + tid];
        swt[tid]  = d_row_weight[rowStart + tid];
    }
    __syncthreads();

    const float* B = wd + (size_t)sE * D_MODEL * D_FF + (size_t)colStart * D_FF;

    float acc[8][4];
#pragma unroll
    for (int i = 0; i < 8; i++)
#pragma unroll
        for (int j = 0; j < 4; j++) acc[i][j] = 0.f;

    const int m0 = (tid >> 4) * 8;
    const int n0 = (tid & 15) * 4;
    const int lr = tid >> 2;
    const int lk = (tid & 3) * 4;

    for (int k0 = 0; k0 < D_FF; k0 += BK) {
#pragma unroll
        for (int it = 0; it < 2; it++) {
            int m = lr + it * 64;
            float4 v = *reinterpret_cast<const float4*>(
                d_H + (size_t)(rowStart + m) * D_FF + k0 + lk);
            As[lk + 0][m] = v.x; As[lk + 1][m] = v.y;
            As[lk + 2][m] = v.z; As[lk + 3][m] = v.w;
        }
        {
            float4 vb = *reinterpret_cast<const float4*>(B + (size_t)lr * D_FF + k0 + lk);
            Bs[lk + 0][lr] = vb.x; Bs[lk + 1][lr] = vb.y;
            Bs[lk + 2][lr] = vb.z; Bs[lk + 3][lr] = vb.w;
        }
        __syncthreads();

#pragma unroll
        for (int k = 0; k < BK; k++) {
            float a[8], b[4];
#pragma unroll
            for (int i = 0; i < 8; i++) a[i] = As[k][m0 + i];
#pragma unroll
            for (int j = 0; j < 4; j++) b[j] = Bs[k][n0 + j];
#pragma unroll
            for (int i = 0; i < 8; i++)
#pragma unroll
                for (int j = 0; j < 4; j++)
                    acc[i][j] = fmaf(a[i], b[j], acc[i][j]);
        }
        __syncthreads();
    }

    // weighted scatter-add: each out element gets exactly 2 contributions
    // (fp32 add is commutative -> deterministic under graph replay)
#pragma unroll
    for (int i = 0; i < 8; i++) {
        int   t = stok[m0 + i];
        float w = swt[m0 + i];
        if (t >= 0) {
            float* orow = out + (size_t)t * D_MODEL + colStart + n0;
#pragma unroll
            for (int j = 0; j < 4; j++)
                atomicAdd(&orow[j], w * acc[i][j]);
        }
    }
}

// ---------------- launch ------------------------------------------------------
extern "C" void kernel_launch(void* const* d_in, const int* in_sizes, int n_in,
                              void* d_out, int out_size) {
    const float* x   = (const float*)d_in[0];
    const float* wr  = (const float*)d_in[1];
    const float* wgu = (const float*)d_in[2];
    const float* wd  = (const float*)d_in[3];
    float* out = (float*)d_out;

    init_kernel<<<2048, 512>>>(out);
    router_kernel<<<N_TOK / 8, 256>>>(x, wr);        // 8 warps/block, 1 warp/token
    offsets_kernel<<<1, 32>>>();
    scatter_kernel<<<(N_TOK + 255) / 256, 256>>>();
    gemm1_kernel<<<dim3(D_FF / BN, ROWS / BM), 256>>>(x, wgu);
    gemm2_kernel<<<dim3(D_MODEL / BN, ROWS / BM), 256>>>(wd, out);
}

// round 8
// speedup vs baseline: 1.7367x; 1.7367x over previous
#include <cuda_runtime.h>
#include <cuda_bf16.h>
#include <math.h>
#include <stdint.h>

#define N_TOK   4096
#define D_MODEL 1024
#define D_FF    2048
#define N_EXP   8
#define ROWS    9216
#define TILE    128
#define LDA     40          /* padded SMEM row stride in bf16 (80B, conflict-free ldmatrix) */

// ===================== helpers ==============================================
__device__ __forceinline__ uint32_t smem_u32(const void* p) {
    uint32_t a;
    asm("{ .reg .u64 t; cvta.to.shared.u64 t, %1; cvt.u32.u64 %0, t; }" : "=r"(a) : "l"(p));
    return a;
}
__device__ __forceinline__ void ldsm_x4(uint32_t& r0, uint32_t& r1, uint32_t& r2, uint32_t& r3,
                                        uint32_t addr) {
    asm volatile("ldmatrix.sync.aligned.m8n8.x4.shared.b16 {%0,%1,%2,%3}, [%4];"
                 : "=r"(r0), "=r"(r1), "=r"(r2), "=r"(r3) : "r"(addr));
}
__device__ __forceinline__ void mma16816(float* c, const uint32_t* a, uint32_t b0, uint32_t b1) {
    asm volatile(
        "mma.sync.aligned.m16n8k16.row.col.f32.bf16.bf16.f32 "
        "{%0,%1,%2,%3}, {%4,%5,%6,%7}, {%8,%9}, {%0,%1,%2,%3};"
        : "+f"(c[0]), "+f"(c[1]), "+f"(c[2]), "+f"(c[3])
        : "r"(a[0]), "r"(a[1]), "r"(a[2]), "r"(a[3]), "r"(b0), "r"(b1));
}

// ===================== scratch ==============================================
__device__ int   d_tok_exp[N_TOK * 2];
__device__ float d_tok_w[N_TOK * 2];
__device__ int   d_count[N_EXP];
__device__ int   d_off[N_EXP + 1];
__device__ int   d_cursor[N_EXP];
__device__ int   d_row_token[ROWS];
__device__ float d_row_weight[ROWS];

__device__ __nv_bfloat16 d_xh[(size_t)N_TOK * D_MODEL];
__device__ __nv_bfloat16 d_xl[(size_t)N_TOK * D_MODEL];
__device__ __nv_bfloat16 d_wguh[(size_t)N_EXP * 2 * D_FF * D_MODEL];
__device__ __nv_bfloat16 d_wgul[(size_t)N_EXP * 2 * D_FF * D_MODEL];
__device__ __nv_bfloat16 d_wdh[(size_t)N_EXP * D_MODEL * D_FF];
__device__ __nv_bfloat16 d_wdl[(size_t)N_EXP * D_MODEL * D_FF];
__device__ __nv_bfloat16 d_Hh[(size_t)ROWS * D_FF];
__device__ __nv_bfloat16 d_Hl[(size_t)ROWS * D_FF];
__device__ float         d_G[(size_t)ROWS * 2 * D_FF];   // raw gate|up, fp32

// ===================== small kernels ========================================
__global__ void init_kernel(float* __restrict__ out) {
    int i = blockIdx.x * blockDim.x + threadIdx.x;
    int stride = gridDim.x * blockDim.x;
    for (int j = i; j < N_TOK * D_MODEL; j += stride) out[j] = 0.f;
    if (i < ROWS) { d_row_token[i] = -1; d_row_weight[i] = 0.f; }
    if (i < N_EXP) d_count[i] = 0;
}

__global__ void split_kernel(const float* __restrict__ s,
                             __nv_bfloat16* __restrict__ hi,
                             __nv_bfloat16* __restrict__ lo, int n4) {
    int i = blockIdx.x * blockDim.x + threadIdx.x;
    if (i >= n4) return;
    float4 v = reinterpret_cast<const float4*>(s)[i];
    __nv_bfloat16 h0 = __float2bfloat16(v.x), h1 = __float2bfloat16(v.y);
    __nv_bfloat16 h2 = __float2bfloat16(v.z), h3 = __float2bfloat16(v.w);
    __nv_bfloat16 l0 = __float2bfloat16(v.x - __bfloat162float(h0));
    __nv_bfloat16 l1 = __float2bfloat16(v.y - __bfloat162float(h1));
    __nv_bfloat16 l2 = __float2bfloat16(v.z - __bfloat162float(h2));
    __nv_bfloat16 l3 = __float2bfloat16(v.w - __bfloat162float(h3));
    reinterpret_cast<__nv_bfloat162*>(hi)[2 * i]     = __halves2bfloat162(h0, h1);
    reinterpret_cast<__nv_bfloat162*>(hi)[2 * i + 1] = __halves2bfloat162(h2, h3);
    reinterpret_cast<__nv_bfloat162*>(lo)[2 * i]     = __halves2bfloat162(l0, l1);
    reinterpret_cast<__nv_bfloat162*>(lo)[2 * i + 1] = __halves2bfloat162(l2, l3);
}

__global__ void router_kernel(const float* __restrict__ x,
                              const float* __restrict__ wr) {
    int warp = (blockIdx.x * blockDim.x + threadIdx.x) >> 5;
    int lane = threadIdx.x & 31;
    if (warp >= N_TOK) return;
    const float* xr = x + (size_t)warp * D_MODEL;

    float logits[N_EXP];
#pragma unroll
    for (int e = 0; e < N_EXP; e++) {
        const float* w = wr + e * D_MODEL;
        float p = 0.f;
        for (int d = lane; d < D_MODEL; d += 32) p = fmaf(xr[d], w[d], p);
#pragma unroll
        for (int s = 16; s > 0; s >>= 1) p += __shfl_xor_sync(0xffffffffu, p, s);
        logits[e] = p;
    }
    if (lane == 0) {
        float mx = -3.4e38f;
#pragma unroll
        for (int e = 0; e < N_EXP; e++) {
            float v = fminf(fmaxf(logits[e], -1e4f), 1e4f);
            logits[e] = v; mx = fmaxf(mx, v);
        }
        float ex[N_EXP], s = 0.f;
#pragma unroll
        for (int e = 0; e < N_EXP; e++) { ex[e] = expf(logits[e] - mx); s += ex[e]; }
        float denom = s + 1e-8f;
        float probs[N_EXP];
#pragma unroll
        for (int e = 0; e < N_EXP; e++)
            probs[e] = fminf(fmaxf(ex[e] / denom, 1e-8f), 1.0f);
        int i0 = 0;
#pragma unroll
        for (int e = 1; e < N_EXP; e++) if (probs[e] > probs[i0]) i0 = e;
        int i1 = (i0 == 0) ? 1 : 0;
#pragma unroll
        for (int e = 0; e < N_EXP; e++)
            if (e != i0 && probs[e] > probs[i1]) i1 = e;
        float p0 = probs[i0], p1 = probs[i1];
        float rs = 1.f / (p0 + p1 + 1e-8f);
        d_tok_exp[2 * warp] = i0;  d_tok_exp[2 * warp + 1] = i1;
        d_tok_w[2 * warp] = p0 * rs; d_tok_w[2 * warp + 1] = p1 * rs;
        atomicAdd(&d_count[i0], 1); atomicAdd(&d_count[i1], 1);
    }
}

__global__ void offsets_kernel() {
    if (threadIdx.x == 0) {
        int o = 0;
        for (int e = 0; e < N_EXP; e++) {
            d_off[e] = o;
            o += ((d_count[e] + TILE - 1) / TILE) * TILE;
            d_cursor[e] = 0;
        }
        d_off[N_EXP] = o;
    }
}

__global__ void scatter_kernel() {
    int t = blockIdx.x * blockDim.x + threadIdx.x;
    if (t >= N_TOK) return;
#pragma unroll
    for (int k = 0; k < 2; k++) {
        int e = d_tok_exp[2 * t + k];
        int pos = d_off[e] + atomicAdd(&d_cursor[e], 1);
        d_row_token[pos]  = t;
        d_row_weight[pos] = d_tok_w[2 * t + k];
    }
}

// ===================== GEMM1: x(gather) @ wgu^T -> d_G (raw fp32) ============
// grid: (4096/128, ROWS/128). K = 1024. 3-term bf16 split HMMA.
__global__ __launch_bounds__(256, 1)
void gemm1_mma(void) {
    __shared__ __align__(16) __nv_bfloat16 Ah[128 * LDA], Al[128 * LDA];
    __shared__ __align__(16) __nv_bfloat16 Bh[128 * LDA], Bl[128 * LDA];
    __shared__ int stok[128];

    const int tid  = threadIdx.x;
    const int wid  = tid >> 5;
    const int lane = tid & 31;
    const int rowStart = blockIdx.y * 128;
    const int colStart = blockIdx.x * 128;   // row of wgu (0..4095): gate|up

    if (rowStart >= d_off[N_EXP]) return;
    int e = 0;
#pragma unroll
    for (int i = N_EXP - 1; i >= 0; i--) if (rowStart >= d_off[i]) { e = i; break; }

    if (tid < 128) stok[tid] = d_row_token[rowStart + tid];
    __syncthreads();

    const size_t wb = (size_t)e * 2 * D_FF * D_MODEL;
    const int wm = (wid & 1) * 64;       // warp row offset
    const int wn = (wid >> 1) * 32;      // warp col offset

    float acc[4][4][4];
#pragma unroll
    for (int a = 0; a < 4; a++)
#pragma unroll
        for (int b = 0; b < 4; b++)
#pragma unroll
            for (int c = 0; c < 4; c++) acc[a][b][c] = 0.f;

    const uint32_t aAh = smem_u32(Ah), aAl = smem_u32(Al);
    const uint32_t aBh = smem_u32(Bh), aBl = smem_u32(Bl);

    for (int kt = 0; kt < D_MODEL / 32; kt++) {
        const int k0 = kt * 32;
#pragma unroll
        for (int i = 0; i < 2; i++) {
            int idx = tid + i * 256;     // 0..511
            int r = idx >> 2;            // 0..127
            int u = idx & 3;             // 16B unit (8 bf16)
            int soff = r * LDA + u * 8;
            int t = stok[r];
            uint4 vh = make_uint4(0u, 0u, 0u, 0u), vl = vh;
            if (t >= 0) {
                size_t g = (size_t)t * D_MODEL + k0 + u * 8;
                vh = *(const uint4*)(d_xh + g);
                vl = *(const uint4*)(d_xl + g);
            }
            *(uint4*)(Ah + soff) = vh;
            *(uint4*)(Al + soff) = vl;
            size_t gb = wb + (size_t)(colStart + r) * D_MODEL + k0 + u * 8;
            *(uint4*)(Bh + soff) = *(const uint4*)(d_wguh + gb);
            *(uint4*)(Bl + soff) = *(const uint4*)(d_wgul + gb);
        }
        __syncthreads();

#pragma unroll
        for (int ks = 0; ks < 2; ks++) {
            const int kk = ks * 16;
            uint32_t fAh[4][4], fAl[4][4], fBh[2][4], fBl[2][4];
#pragma unroll
            for (int mt = 0; mt < 4; mt++) {
                uint32_t off = (uint32_t)(((wm + mt * 16 + (lane & 15)) * LDA
                                           + kk + (lane >> 4) * 8) * 2);
                ldsm_x4(fAh[mt][0], fAh[mt][1], fAh[mt][2], fAh[mt][3], aAh + off);
                ldsm_x4(fAl[mt][0], fAl[mt][1], fAl[mt][2], fAl[mt][3], aAl + off);
            }
#pragma unroll
            for (int p = 0; p < 2; p++) {
                int n0 = wn + p * 16;
                uint32_t off = (uint32_t)(((n0 + (lane & 7) + (lane >> 4) * 8) * LDA
                                           + kk + ((lane >> 3) & 1) * 8) * 2);
                ldsm_x4(fBh[p][0], fBh[p][1], fBh[p][2], fBh[p][3], aBh + off);
                ldsm_x4(fBl[p][0], fBl[p][1], fBl[p][2], fBl[p][3], aBl + off);
            }
#pragma unroll
            for (int mt = 0; mt < 4; mt++)
#pragma unroll
                for (int nb = 0; nb < 4; nb++) {
                    int p = nb >> 1, h = (nb & 1) * 2;
                    mma16816(acc[mt][nb], fAh[mt], fBh[p][h], fBh[p][h + 1]);
                    mma16816(acc[mt][nb], fAh[mt], fBl[p][h], fBl[p][h + 1]);
                    mma16816(acc[mt][nb], fAl[mt], fBh[p][h], fBh[p][h + 1]);
                }
        }
        __syncthreads();
    }

    // epilogue: raw fp32 to d_G
    const int g  = lane >> 2;
    const int c2 = (lane & 3) * 2;
#pragma unroll
    for (int mt = 0; mt < 4; mt++) {
        int row0 = rowStart + wm + mt * 16 + g;
#pragma unroll
        for (int nb = 0; nb < 4; nb++) {
            int col = colStart + wn + nb * 8 + c2;
            float2 v0 = make_float2(acc[mt][nb][0], acc[mt][nb][1]);
            float2 v1 = make_float2(acc[mt][nb][2], acc[mt][nb][3]);
            *(float2*)(d_G + (size_t)row0 * (2 * D_FF) + col)       = v0;
            *(float2*)(d_G + (size_t)(row0 + 8) * (2 * D_FF) + col) = v1;
        }
    }
}

// ===================== SwiGLU: d_G -> Hh/Hl (bf16 split) =====================
__global__ void swiglu_kernel(void) {
    int idx = blockIdx.x * blockDim.x + threadIdx.x;
    const int total = ROWS * (D_FF / 4);
    if (idx >= total) return;
    int row = idx / (D_FF / 4);
    int f4  = idx % (D_FF / 4);
    size_t gb = (size_t)row * (2 * D_FF) + f4 * 4;
    float4 gv = *(const float4*)(d_G + gb);
    float4 uv = *(const float4*)(d_G + gb + D_FF);
    float h[4];
    h[0] = gv.x * uv.x / (1.f + expf(-uv.x));
    h[1] = gv.y * uv.y / (1.f + expf(-uv.y));
    h[2] = gv.z * uv.z / (1.f + expf(-uv.z));
    h[3] = gv.w * uv.w / (1.f + expf(-uv.w));
    size_t hb = (size_t)row * D_FF + f4 * 4;
#pragma unroll
    for (int j = 0; j < 4; j += 2) {
        __nv_bfloat16 a0 = __float2bfloat16(h[j]);
        __nv_bfloat16 a1 = __float2bfloat16(h[j + 1]);
        __nv_bfloat16 b0 = __float2bfloat16(h[j] - __bfloat162float(a0));
        __nv_bfloat16 b1 = __float2bfloat16(h[j + 1] - __bfloat162float(a1));
        *reinterpret_cast<__nv_bfloat162*>(d_Hh + hb + j) = __halves2bfloat162(a0, a1);
        *reinterpret_cast<__nv_bfloat162*>(d_Hl + hb + j) = __halves2bfloat162(b0, b1);
    }
}

// ===================== GEMM2: H @ wd^T -> weighted scatter ===================
// grid: (1024/128, ROWS/128). K = 2048.
__global__ __launch_bounds__(256, 1)
void gemm2_mma(float* __restrict__ out) {
    __shared__ __align__(16) __nv_bfloat16 Ah[128 * LDA], Al[128 * LDA];
    __shared__ __align__(16) __nv_bfloat16 Bh[128 * LDA], Bl[128 * LDA];
    __shared__ int   stok[128];
    __shared__ float swt[128];

    const int tid  = threadIdx.x;
    const int wid  = tid >> 5;
    const int lane = tid & 31;
    const int rowStart = blockIdx.y * 128;
    const int colStart = blockIdx.x * 128;   // d col (0..1023)

    if (rowStart >= d_off[N_EXP]) return;
    int e = 0;
#pragma unroll
    for (int i = N_EXP - 1; i >= 0; i--) if (rowStart >= d_off[i]) { e = i; break; }

    if (tid < 128) {
        stok[tid] = d_row_token[rowStart + tid];
        swt[tid]  = d_row_weight[rowStart + tid];
    }
    __syncthreads();

    const size_t wb = (size_t)e * D_MODEL * D_FF;
    const int wm = (wid & 1) * 64;
    const int wn = (wid >> 1) * 32;

    float acc[4][4][4];
#pragma unroll
    for (int a = 0; a < 4; a++)
#pragma unroll
        for (int b = 0; b < 4; b++)
#pragma unroll
            for (int c = 0; c < 4; c++) acc[a][b][c] = 0.f;

    const uint32_t aAh = smem_u32(Ah), aAl = smem_u32(Al);
    const uint32_t aBh = smem_u32(Bh), aBl = smem_u32(Bl);

    for (int kt = 0; kt < D_FF / 32; kt++) {
        const int k0 = kt * 32;
#pragma unroll
        for (int i = 0; i < 2; i++) {
            int idx = tid + i * 256;
            int r = idx >> 2;
            int u = idx & 3;
            int soff = r * LDA + u * 8;
            size_t ga = (size_t)(rowStart + r) * D_FF + k0 + u * 8;
            *(uint4*)(Ah + soff) = *(const uint4*)(d_Hh + ga);
            *(uint4*)(Al + soff) = *(const uint4*)(d_Hl + ga);
            size_t gb = wb + (size_t)(colStart + r) * D_FF + k0 + u * 8;
            *(uint4*)(Bh + soff) = *(const uint4*)(d_wdh + gb);
            *(uint4*)(Bl + soff) = *(const uint4*)(d_wdl + gb);
        }
        __syncthreads();

#pragma unroll
        for (int ks = 0; ks < 2; ks++) {
            const int kk = ks * 16;
            uint32_t fAh[4][4], fAl[4][4], fBh[2][4], fBl[2][4];
#pragma unroll
            for (int mt = 0; mt < 4; mt++) {
                uint32_t off = (uint32_t)(((wm + mt * 16 + (lane & 15)) * LDA
                                           + kk + (lane >> 4) * 8) * 2);
                ldsm_x4(fAh[mt][0], fAh[mt][1], fAh[mt][2], fAh[mt][3], aAh + off);
                ldsm_x4(fAl[mt][0], fAl[mt][1], fAl[mt][2], fAl[mt][3], aAl + off);
            }
#pragma unroll
            for (int p = 0; p < 2; p++) {
                int n0 = wn + p * 16;
                uint32_t off = (uint32_t)(((n0 + (lane & 7) + (lane >> 4) * 8) * LDA
                                           + kk + ((lane >> 3) & 1) * 8) * 2);
                ldsm_x4(fBh[p][0], fBh[p][1], fBh[p][2], fBh[p][3], aBh + off);
                ldsm_x4(fBl[p][0], fBl[p][1], fBl[p][2], fBl[p][3], aBl + off);
            }
#pragma unroll
            for (int mt = 0; mt < 4; mt++)
#pragma unroll
                for (int nb = 0; nb < 4; nb++) {
                    int p = nb >> 1, h = (nb & 1) * 2;
                    mma16816(acc[mt][nb], fAh[mt], fBh[p][h], fBh[p][h + 1]);
                    mma16816(acc[mt][nb], fAh[mt], fBl[p][h], fBl[p][h + 1]);
                    mma16816(acc[mt][nb], fAl[mt], fBh[p][h], fBh[p][h + 1]);
                }
        }
        __syncthreads();
    }

    // epilogue: weighted scatter-add (each out element gets exactly 2 fp32 adds)
    const int g  = lane >> 2;
    const int c2 = (lane & 3) * 2;
#pragma unroll
    for (int mt = 0; mt < 4; mt++) {
        int r0 = wm + mt * 16 + g;
        int t0 = stok[r0],     t1 = stok[r0 + 8];
        float w0 = swt[r0],    w1 = swt[r0 + 8];
#pragma unroll
        for (int nb = 0; nb < 4; nb++) {
            int col = colStart + wn + nb * 8 + c2;
            if (t0 >= 0) {
                float* o = out + (size_t)t0 * D_MODEL + col;
                atomicAdd(o,     w0 * acc[mt][nb][0]);
                atomicAdd(o + 1, w0 * acc[mt][nb][1]);
            }
            if (t1 >= 0) {
                float* o = out + (size_t)t1 * D_MODEL + col;
                atomicAdd(o,     w1 * acc[mt][nb][2]);
                atomicAdd(o + 1, w1 * acc[mt][nb][3]);
            }
        }
    }
}

// ===================== launch ================================================
extern "C" void kernel_launch(void* const* d_in, const int* in_sizes, int n_in,
                              void* d_out, int out_size) {
    const float* x   = (const float*)d_in[0];
    const float* wr  = (const float*)d_in[1];
    const float* wgu = (const float*)d_in[2];
    const float* wd  = (const float*)d_in[3];
    float* out = (float*)d_out;

    init_kernel<<<2048, 512>>>(out);

    __nv_bfloat16 *xh, *xl, *wguh, *wgul, *wdh, *wdl;
    cudaGetSymbolAddress((void**)&xh,   d_xh);
    cudaGetSymbolAddress((void**)&xl,   d_xl);
    cudaGetSymbolAddress((void**)&wguh, d_wguh);
    cudaGetSymbolAddress((void**)&wgul, d_wgul);
    cudaGetSymbolAddress((void**)&wdh,  d_wdh);
    cudaGetSymbolAddress((void**)&wdl,  d_wdl);

    { int n4 = N_TOK * D_MODEL / 4;
      split_kernel<<<(n4 + 255) / 256, 256>>>(x, xh, xl, n4); }
    { int n4 = N_EXP * 2 * D_FF * D_MODEL / 4;
      split_kernel<<<(n4 + 255) / 256, 256>>>(wgu, wguh, wgul, n4); }
    { int n4 = N_EXP * D_MODEL * D_FF / 4;
      split_kernel<<<(n4 + 255) / 256, 256>>>(wd, wdh, wdl, n4); }

    router_kernel<<<N_TOK / 8, 256>>>(x, wr);
    offsets_kernel<<<1, 32>>>();
    scatter_kernel<<<(N_TOK + 255) / 256, 256>>>();

    gemm1_mma<<<dim3(2 * D_FF / 128, ROWS / 128), 256>>>();
    { int n = ROWS * (D_FF / 4);
      swiglu_kernel<<<(n + 255) / 256, 256>>>(); }
    gemm2_mma<<<dim3(D_MODEL / 128, ROWS / 128), 256>>>(out);
}

// round 10
// speedup vs baseline: 2.3135x; 1.3321x over previous
#include <cuda_runtime.h>
#include <cuda_bf16.h>
#include <math.h>
#include <stdint.h>

#define N_TOK   4096
#define D_MODEL 1024
#define D_FF    2048
#define N_EXP   8
#define ROWS    9216
#define TILE    128
#define LDA     40          /* padded SMEM row stride in bf16 (80B, conflict-free ldmatrix) */

#define BUF_BYTES   (128 * LDA * 2)          /* 10240 B per tile buffer */
#define AH_OFF      0
#define AL_OFF      (1 * BUF_BYTES)
#define BH_OFF      (2 * BUF_BYTES)
#define BL_OFF      (3 * BUF_BYTES)
#define STAGE_BYTES (4 * BUF_BYTES)          /* 40960 B */
#define DSMEM_BYTES (2 * STAGE_BYTES)        /* 81920 B */

// ===================== helpers ==============================================
__device__ __forceinline__ uint32_t smem_u32(const void* p) {
    uint32_t a;
    asm("{ .reg .u64 t; cvta.to.shared.u64 t, %1; cvt.u32.u64 %0, t; }" : "=r"(a) : "l"(p));
    return a;
}
__device__ __forceinline__ void ldsm_x4(uint32_t& r0, uint32_t& r1, uint32_t& r2, uint32_t& r3,
                                        uint32_t addr) {
    asm volatile("ldmatrix.sync.aligned.m8n8.x4.shared.b16 {%0,%1,%2,%3}, [%4];"
                 : "=r"(r0), "=r"(r1), "=r"(r2), "=r"(r3) : "r"(addr));
}
__device__ __forceinline__ void mma16816(float* c, const uint32_t* a, uint32_t b0, uint32_t b1) {
    asm volatile(
        "mma.sync.aligned.m16n8k16.row.col.f32.bf16.bf16.f32 "
        "{%0,%1,%2,%3}, {%4,%5,%6,%7}, {%8,%9}, {%0,%1,%2,%3};"
        : "+f"(c[0]), "+f"(c[1]), "+f"(c[2]), "+f"(c[3])
        : "r"(a[0]), "r"(a[1]), "r"(a[2]), "r"(a[3]), "r"(b0), "r"(b1));
}
__device__ __forceinline__ void cp16(uint32_t saddr, const void* g, uint32_t src_sz) {
    asm volatile("cp.async.cg.shared.global [%0], [%1], 16, %2;"
                 :: "r"(saddr), "l"(g), "r"(src_sz));
}
#define CP_COMMIT() asm volatile("cp.async.commit_group;" ::: "memory")
#define CP_WAIT1()  asm volatile("cp.async.wait_group 1;" ::: "memory")

// ===================== scratch ==============================================
__device__ int   d_tok_exp[N_TOK * 2];
__device__ float d_tok_w[N_TOK * 2];
__device__ int   d_count[N_EXP];
__device__ int   d_off[N_EXP + 1];
__device__ int   d_cursor[N_EXP];
__device__ int   d_row_token[ROWS];
__device__ float d_row_weight[ROWS];

__device__ __nv_bfloat16 d_xh[(size_t)N_TOK * D_MODEL];
__device__ __nv_bfloat16 d_xl[(size_t)N_TOK * D_MODEL];
__device__ __nv_bfloat16 d_wguh[(size_t)N_EXP * 2 * D_FF * D_MODEL];
__device__ __nv_bfloat16 d_wgul[(size_t)N_EXP * 2 * D_FF * D_MODEL];
__device__ __nv_bfloat16 d_wdh[(size_t)N_EXP * D_MODEL * D_FF];
__device__ __nv_bfloat16 d_wdl[(size_t)N_EXP * D_MODEL * D_FF];
__device__ __nv_bfloat16 d_Hh[(size_t)ROWS * D_FF];
__device__ __nv_bfloat16 d_Hl[(size_t)ROWS * D_FF];
__device__ float         d_G[(size_t)ROWS * 2 * D_FF];   // raw gate|up, fp32

// ===================== small kernels ========================================
__global__ void init_kernel(float* __restrict__ out) {
    int i = blockIdx.x * blockDim.x + threadIdx.x;
    int stride = gridDim.x * blockDim.x;
    for (int j = i; j < N_TOK * D_MODEL; j += stride) out[j] = 0.f;
    if (i < ROWS) { d_row_token[i] = -1; d_row_weight[i] = 0.f; }
    if (i < N_EXP) d_count[i] = 0;
}

__global__ void split_kernel(const float* __restrict__ s,
                             __nv_bfloat16* __restrict__ hi,
                             __nv_bfloat16* __restrict__ lo, int n4) {
    int i = blockIdx.x * blockDim.x + threadIdx.x;
    if (i >= n4) return;
    float4 v = reinterpret_cast<const float4*>(s)[i];
    __nv_bfloat16 h0 = __float2bfloat16(v.x), h1 = __float2bfloat16(v.y);
    __nv_bfloat16 h2 = __float2bfloat16(v.z), h3 = __float2bfloat16(v.w);
    __nv_bfloat16 l0 = __float2bfloat16(v.x - __bfloat162float(h0));
    __nv_bfloat16 l1 = __float2bfloat16(v.y - __bfloat162float(h1));
    __nv_bfloat16 l2 = __float2bfloat16(v.z - __bfloat162float(h2));
    __nv_bfloat16 l3 = __float2bfloat16(v.w - __bfloat162float(h3));
    reinterpret_cast<__nv_bfloat162*>(hi)[2 * i]     = __halves2bfloat162(h0, h1);
    reinterpret_cast<__nv_bfloat162*>(hi)[2 * i + 1] = __halves2bfloat162(h2, h3);
    reinterpret_cast<__nv_bfloat162*>(lo)[2 * i]     = __halves2bfloat162(l0, l1);
    reinterpret_cast<__nv_bfloat162*>(lo)[2 * i + 1] = __halves2bfloat162(l2, l3);
}

__global__ void router_kernel(const float* __restrict__ x,
                              const float* __restrict__ wr) {
    int warp = (blockIdx.x * blockDim.x + threadIdx.x) >> 5;
    int lane = threadIdx.x & 31;
    if (warp >= N_TOK) return;
    const float* xr = x + (size_t)warp * D_MODEL;

    float logits[N_EXP];
#pragma unroll
    for (int e = 0; e < N_EXP; e++) {
        const float* w = wr + e * D_MODEL;
        float p = 0.f;
        for (int d = lane; d < D_MODEL; d += 32) p = fmaf(xr[d], w[d], p);
#pragma unroll
        for (int s = 16; s > 0; s >>= 1) p += __shfl_xor_sync(0xffffffffu, p, s);
        logits[e] = p;
    }
    if (lane == 0) {
        float mx = -3.4e38f;
#pragma unroll
        for (int e = 0; e < N_EXP; e++) {
            float v = fminf(fmaxf(logits[e], -1e4f), 1e4f);
            logits[e] = v; mx = fmaxf(mx, v);
        }
        float ex[N_EXP], s = 0.f;
#pragma unroll
        for (int e = 0; e < N_EXP; e++) { ex[e] = expf(logits[e] - mx); s += ex[e]; }
        float denom = s + 1e-8f;
        float probs[N_EXP];
#pragma unroll
        for (int e = 0; e < N_EXP; e++)
            probs[e] = fminf(fmaxf(ex[e] / denom, 1e-8f), 1.0f);
        int i0 = 0;
#pragma unroll
        for (int e = 1; e < N_EXP; e++) if (probs[e] > probs[i0]) i0 = e;
        int i1 = (i0 == 0) ? 1 : 0;
#pragma unroll
        for (int e = 0; e < N_EXP; e++)
            if (e != i0 && probs[e] > probs[i1]) i1 = e;
        float p0 = probs[i0], p1 = probs[i1];
        float rs = 1.f / (p0 + p1 + 1e-8f);
        d_tok_exp[2 * warp] = i0;  d_tok_exp[2 * warp + 1] = i1;
        d_tok_w[2 * warp] = p0 * rs; d_tok_w[2 * warp + 1] = p1 * rs;
        atomicAdd(&d_count[i0], 1); atomicAdd(&d_count[i1], 1);
    }
}

__global__ void offsets_kernel() {
    if (threadIdx.x == 0) {
        int o = 0;
        for (int e = 0; e < N_EXP; e++) {
            d_off[e] = o;
            o += ((d_count[e] + TILE - 1) / TILE) * TILE;
            d_cursor[e] = 0;
        }
        d_off[N_EXP] = o;
    }
}

__global__ void scatter_kernel() {
    int t = blockIdx.x * blockDim.x + threadIdx.x;
    if (t >= N_TOK) return;
#pragma unroll
    for (int k = 0; k < 2; k++) {
        int e = d_tok_exp[2 * t + k];
        int pos = d_off[e] + atomicAdd(&d_cursor[e], 1);
        d_row_token[pos]  = t;
        d_row_weight[pos] = d_tok_w[2 * t + k];
    }
}

// ===================== GEMM1: x(gather) @ wgu^T -> d_G (raw fp32) ============
// grid: (4096/128, ROWS/128). K = 1024. cp.async double-buffered.
__global__ __launch_bounds__(256, 1)
void gemm1_mma(void) {
    extern __shared__ __align__(16) char dyn[];
    __shared__ int stok[128];

    const int tid  = threadIdx.x;
    const int wid  = tid >> 5;
    const int lane = tid & 31;
    const int rowStart = blockIdx.y * 128;
    const int colStart = blockIdx.x * 128;   // row of wgu (0..4095): gate|up

    if (rowStart >= d_off[N_EXP]) return;
    int e = 0;
#pragma unroll
    for (int i = N_EXP - 1; i >= 0; i--) if (rowStart >= d_off[i]) { e = i; break; }

    if (tid < 128) stok[tid] = d_row_token[rowStart + tid];
    __syncthreads();

    const size_t wb = (size_t)e * 2 * D_FF * D_MODEL;
    const int wm = (wid & 1) * 64;
    const int wn = (wid >> 1) * 32;
    const uint32_t base = smem_u32(dyn);

    // per-thread load coords (8 cp16 per stage: 2 row-chunks x 4 buffers)
    const int r0_ = tid >> 2, r1_ = r0_ + 64;
    const int u_  = tid & 3;

    float acc[4][4][4];
#pragma unroll
    for (int a = 0; a < 4; a++)
#pragma unroll
        for (int b = 0; b < 4; b++)
#pragma unroll
            for (int c = 0; c < 4; c++) acc[a][b][c] = 0.f;

#define G1_LOAD(stage, kt) do {                                                   \
    const uint32_t sb = base + (stage) * STAGE_BYTES;                             \
    const int k0 = (kt) * 32;                                                     \
    _Pragma("unroll")                                                             \
    for (int i = 0; i < 2; i++) {                                                 \
        int r = i ? r1_ : r0_;                                                    \
        uint32_t so = (uint32_t)((r * LDA + u_ * 8) * 2);                         \
        int t = stok[r];                                                          \
        uint32_t sz = (t >= 0) ? 16u : 0u;                                        \
        size_t ga = (size_t)(t >= 0 ? t : 0) * D_MODEL + k0 + u_ * 8;             \
        cp16(sb + AH_OFF + so, d_xh + ga, sz);                                    \
        cp16(sb + AL_OFF + so, d_xl + ga, sz);                                    \
        size_t gb = wb + (size_t)(colStart + r) * D_MODEL + k0 + u_ * 8;          \
        cp16(sb + BH_OFF + so, d_wguh + gb, 16u);                                 \
        cp16(sb + BL_OFF + so, d_wgul + gb, 16u);                                 \
    }                                                                             \
} while (0)

    G1_LOAD(0, 0);
    CP_COMMIT();

    const int NKT = D_MODEL / 32;
#pragma unroll 1
    for (int kt = 0; kt < NKT; kt++) {
        if (kt + 1 < NKT) G1_LOAD((kt + 1) & 1, kt + 1);
        CP_COMMIT();
        CP_WAIT1();
        __syncthreads();

        const uint32_t sb  = base + (kt & 1) * STAGE_BYTES;
        const uint32_t aAh = sb + AH_OFF, aAl = sb + AL_OFF;
        const uint32_t aBh = sb + BH_OFF, aBl = sb + BL_OFF;
#pragma unroll
        for (int ks = 0; ks < 2; ks++) {
            const int kk = ks * 16;
            uint32_t fAh[4][4], fAl[4][4], fBh[2][4], fBl[2][4];
#pragma unroll
            for (int mt = 0; mt < 4; mt++) {
                uint32_t off = (uint32_t)(((wm + mt * 16 + (lane & 15)) * LDA
                                           + kk + (lane >> 4) * 8) * 2);
                ldsm_x4(fAh[mt][0], fAh[mt][1], fAh[mt][2], fAh[mt][3], aAh + off);
                ldsm_x4(fAl[mt][0], fAl[mt][1], fAl[mt][2], fAl[mt][3], aAl + off);
            }
#pragma unroll
            for (int p = 0; p < 2; p++) {
                int n0 = wn + p * 16;
                uint32_t off = (uint32_t)(((n0 + (lane & 7) + (lane >> 4) * 8) * LDA
                                           + kk + ((lane >> 3) & 1) * 8) * 2);
                ldsm_x4(fBh[p][0], fBh[p][1], fBh[p][2], fBh[p][3], aBh + off);
                ldsm_x4(fBl[p][0], fBl[p][1], fBl[p][2], fBl[p][3], aBl + off);
            }
#pragma unroll
            for (int mt = 0; mt < 4; mt++)
#pragma unroll
                for (int nb = 0; nb < 4; nb++) {
                    int p = nb >> 1, h = (nb & 1) * 2;
                    mma16816(acc[mt][nb], fAh[mt], fBh[p][h], fBh[p][h + 1]);
                    mma16816(acc[mt][nb], fAh[mt], fBl[p][h], fBl[p][h + 1]);
                    mma16816(acc[mt][nb], fAl[mt], fBh[p][h], fBh[p][h + 1]);
                }
        }
        __syncthreads();
    }
#undef G1_LOAD

    // epilogue: raw fp32 to d_G
    const int g  = lane >> 2;
    const int c2 = (lane & 3) * 2;
#pragma unroll
    for (int mt = 0; mt < 4; mt++) {
        int row0 = rowStart + wm + mt * 16 + g;
#pragma unroll
        for (int nb = 0; nb < 4; nb++) {
            int col = colStart + wn + nb * 8 + c2;
            float2 v0 = make_float2(acc[mt][nb][0], acc[mt][nb][1]);
            float2 v1 = make_float2(acc[mt][nb][2], acc[mt][nb][3]);
            *(float2*)(d_G + (size_t)row0 * (2 * D_FF) + col)       = v0;
            *(float2*)(d_G + (size_t)(row0 + 8) * (2 * D_FF) + col) = v1;
        }
    }
}

// ===================== SwiGLU: d_G -> Hh/Hl (bf16 split) =====================
__global__ void swiglu_kernel(void) {
    int idx = blockIdx.x * blockDim.x + threadIdx.x;
    const int total = ROWS * (D_FF / 4);
    if (idx >= total) return;
    int row = idx / (D_FF / 4);
    int f4  = idx % (D_FF / 4);
    size_t gb = (size_t)row * (2 * D_FF) + f4 * 4;
    float4 gv = *(const float4*)(d_G + gb);
    float4 uv = *(const float4*)(d_G + gb + D_FF);
    float h[4];
    h[0] = gv.x * uv.x / (1.f + expf(-uv.x));
    h[1] = gv.y * uv.y / (1.f + expf(-uv.y));
    h[2] = gv.z * uv.z / (1.f + expf(-uv.z));
    h[3] = gv.w * uv.w / (1.f + expf(-uv.w));
    size_t hb = (size_t)row * D_FF + f4 * 4;
#pragma unroll
    for (int j = 0; j < 4; j += 2) {
        __nv_bfloat16 a0 = __float2bfloat16(h[j]);
        __nv_bfloat16 a1 = __float2bfloat16(h[j + 1]);
        __nv_bfloat16 b0 = __float2bfloat16(h[j] - __bfloat162float(a0));
        __nv_bfloat16 b1 = __float2bfloat16(h[j + 1] - __bfloat162float(a1));
        *reinterpret_cast<__nv_bfloat162*>(d_Hh + hb + j) = __halves2bfloat162(a0, a1);
        *reinterpret_cast<__nv_bfloat162*>(d_Hl + hb + j) = __halves2bfloat162(b0, b1);
    }
}

// ===================== GEMM2: H @ wd^T -> weighted scatter ===================
// grid: (1024/128, ROWS/128). K = 2048. cp.async double-buffered.
__global__ __launch_bounds__(256, 1)
void gemm2_mma(float* __restrict__ out) {
    extern __shared__ __align__(16) char dyn[];
    __shared__ int   stok[128];
    __shared__ float swt[128];

    const int tid  = threadIdx.x;
    const int wid  = tid >> 5;
    const int lane = tid & 31;
    const int rowStart = blockIdx.y * 128;
    const int colStart = blockIdx.x * 128;   // d col (0..1023)

    if (rowStart >= d_off[N_EXP]) return;
    int e = 0;
#pragma unroll
    for (int i = N_EXP - 1; i >= 0; i--) if (rowStart >= d_off[i]) { e = i; break; }

    if (tid < 128) {
        stok[tid] = d_row_token[rowStart + tid];
        swt[tid]  = d_row_weight[rowStart + tid];
    }
    __syncthreads();

    const size_t wb = (size_t)e * D_MODEL * D_FF;
    const int wm = (wid & 1) * 64;
    const int wn = (wid >> 1) * 32;
    const uint32_t base = smem_u32(dyn);

    const int r0_ = tid >> 2, r1_ = r0_ + 64;
    const int u_  = tid & 3;

    float acc[4][4][4];
#pragma unroll
    for (int a = 0; a < 4; a++)
#pragma unroll
        for (int b = 0; b < 4; b++)
#pragma unroll
            for (int c = 0; c < 4; c++) acc[a][b][c] = 0.f;

#define G2_LOAD(stage, kt) do {                                                   \
    const uint32_t sb = base + (stage) * STAGE_BYTES;                             \
    const int k0 = (kt) * 32;                                                     \
    _Pragma("unroll")                                                             \
    for (int i = 0; i < 2; i++) {                                                 \
        int r = i ? r1_ : r0_;                                                    \
        uint32_t so = (uint32_t)((r * LDA + u_ * 8) * 2);                         \
        size_t ga = (size_t)(rowStart + r) * D_FF + k0 + u_ * 8;                  \
        cp16(sb + AH_OFF + so, d_Hh + ga, 16u);                                   \
        cp16(sb + AL_OFF + so, d_Hl + ga, 16u);                                   \
        size_t gb = wb + (size_t)(colStart + r) * D_FF + k0 + u_ * 8;             \
        cp16(sb + BH_OFF + so, d_wdh + gb, 16u);                                  \
        cp16(sb + BL_OFF + so, d_wdl + gb, 16u);                                  \
    }                                                                             \
} while (0)

    G2_LOAD(0, 0);
    CP_COMMIT();

    const int NKT = D_FF / 32;
#pragma unroll 1
    for (int kt = 0; kt < NKT; kt++) {
        if (kt + 1 < NKT) G2_LOAD((kt + 1) & 1, kt + 1);
        CP_COMMIT();
        CP_WAIT1();
        __syncthreads();

        const uint32_t sb  = base + (kt & 1) * STAGE_BYTES;
        const uint32_t aAh = sb + AH_OFF, aAl = sb + AL_OFF;
        const uint32_t aBh = sb + BH_OFF, aBl = sb + BL_OFF;
#pragma unroll
        for (int ks = 0; ks < 2; ks++) {
            const int kk = ks * 16;
            uint32_t fAh[4][4], fAl[4][4], fBh[2][4], fBl[2][4];
#pragma unroll
            for (int mt = 0; mt < 4; mt++) {
                uint32_t off = (uint32_t)(((wm + mt * 16 + (lane & 15)) * LDA
                                           + kk + (lane >> 4) * 8) * 2);
                ldsm_x4(fAh[mt][0], fAh[mt][1], fAh[mt][2], fAh[mt][3], aAh + off);
                ldsm_x4(fAl[mt][0], fAl[mt][1], fAl[mt][2], fAl[mt][3], aAl + off);
            }
#pragma unroll
            for (int p = 0; p < 2; p++) {
                int n0 = wn + p * 16;
                uint32_t off = (uint32_t)(((n0 + (lane & 7) + (lane >> 4) * 8) * LDA
                                           + kk + ((lane >> 3) & 1) * 8) * 2);
                ldsm_x4(fBh[p][0], fBh[p][1], fBh[p][2], fBh[p][3], aBh + off);
                ldsm_x4(fBl[p][0], fBl[p][1], fBl[p][2], fBl[p][3], aBl + off);
            }
#pragma unroll
            for (int mt = 0; mt < 4; mt++)
#pragma unroll
                for (int nb = 0; nb < 4; nb++) {
                    int p = nb >> 1, h = (nb & 1) * 2;
                    mma16816(acc[mt][nb], fAh[mt], fBh[p][h], fBh[p][h + 1]);
                    mma16816(acc[mt][nb], fAh[mt], fBl[p][h], fBl[p][h + 1]);
                    mma16816(acc[mt][nb], fAl[mt], fBh[p][h], fBh[p][h + 1]);
                }
        }
        __syncthreads();
    }
#undef G2_LOAD

    // epilogue: weighted scatter-add (each out element gets exactly 2 fp32 adds)
    const int g  = lane >> 2;
    const int c2 = (lane & 3) * 2;
#pragma unroll
    for (int mt = 0; mt < 4; mt++) {
        int r0 = wm + mt * 16 + g;
        int t0 = stok[r0],     t1 = stok[r0 + 8];
        float w0 = swt[r0],    w1 = swt[r0 + 8];
#pragma unroll
        for (int nb = 0; nb < 4; nb++) {
            int col = colStart + wn + nb * 8 + c2;
            if (t0 >= 0) {
                float* o = out + (size_t)t0 * D_MODEL + col;
                atomicAdd(o,     w0 * acc[mt][nb][0]);
                atomicAdd(o + 1, w0 * acc[mt][nb][1]);
            }
            if (t1 >= 0) {
                float* o = out + (size_t)t1 * D_MODEL + col;
                atomicAdd(o,     w1 * acc[mt][nb][2]);
                atomicAdd(o + 1, w1 * acc[mt][nb][3]);
            }
        }
    }
}

// ===================== launch ================================================
extern "C" void kernel_launch(void* const* d_in, const int* in_sizes, int n_in,
                              void* d_out, int out_size) {
    const float* x   = (const float*)d_in[0];
    const float* wr  = (const float*)d_in[1];
    const float* wgu = (const float*)d_in[2];
    const float* wd  = (const float*)d_in[3];
    float* out = (float*)d_out;

    cudaFuncSetAttribute(gemm1_mma, cudaFuncAttributeMaxDynamicSharedMemorySize, DSMEM_BYTES);
    cudaFuncSetAttribute(gemm2_mma, cudaFuncAttributeMaxDynamicSharedMemorySize, DSMEM_BYTES);

    init_kernel<<<2048, 512>>>(out);

    __nv_bfloat16 *xh, *xl, *wguh, *wgul, *wdh, *wdl;
    cudaGetSymbolAddress((void**)&xh,   d_xh);
    cudaGetSymbolAddress((void**)&xl,   d_xl);
    cudaGetSymbolAddress((void**)&wguh, d_wguh);
    cudaGetSymbolAddress((void**)&wgul, d_wgul);
    cudaGetSymbolAddress((void**)&wdh,  d_wdh);
    cudaGetSymbolAddress((void**)&wdl,  d_wdl);

    { int n4 = N_TOK * D_MODEL / 4;
      split_kernel<<<(n4 + 255) / 256, 256>>>(x, xh, xl, n4); }
    { int n4 = N_EXP * 2 * D_FF * D_MODEL / 4;
      split_kernel<<<(n4 + 255) / 256, 256>>>(wgu, wguh, wgul, n4); }
    { int n4 = N_EXP * D_MODEL * D_FF / 4;
      split_kernel<<<(n4 + 255) / 256, 256>>>(wd, wdh, wdl, n4); }

    router_kernel<<<N_TOK / 8, 256>>>(x, wr);
    offsets_kernel<<<1, 32>>>();
    scatter_kernel<<<(N_TOK + 255) / 256, 256>>>();

    gemm1_mma<<<dim3(2 * D_FF / 128, ROWS / 128), 256, DSMEM_BYTES>>>();
    { int n = ROWS * (D_FF / 4);
      swiglu_kernel<<<(n + 255) / 256, 256>>>(); }
    gemm2_mma<<<dim3(D_MODEL / 128, ROWS / 128), 256, DSMEM_BYTES>>>(out);
}